// round 13
// baseline (speedup 1.0000x reference)
#include <cuda_runtime.h>
#include <cstdint>

#define BATCH 4
#define TSEQ  4096
#define DM    1024
#define HS    128
#define NROWS (BATCH*TSEQ)

// Scratch (cudaMalloc forbidden). Q pre-scaled by log2(e)/sqrt(128) so softmax
// is a bare ex2; Q/K/V all tf32-rounded at projection epilogue.
__device__ float g_Q[NROWS * HS];
__device__ float g_K[NROWS * HS];
__device__ float g_V[NROWS * HS];

__device__ __forceinline__ uint32_t f2tf(float f) {
    uint32_t u; asm("cvt.rna.tf32.f32 %0, %1;" : "=r"(u) : "f"(f)); return u;
}
__device__ __forceinline__ float ex2(float x) {
    float y; asm("ex2.approx.f32 %0, %1;" : "=f"(y) : "f"(x)); return y;
}
__device__ __forceinline__ uint32_t smem_u32(const void* p) {
    uint32_t a; asm("{ .reg .u64 t; cvta.to.shared.u64 t, %1; cvt.u32.u64 %0, t; }" : "=r"(a) : "l"(p));
    return a;
}
__device__ __forceinline__ void cpa16(uint32_t dst, const void* src) {
    asm volatile("cp.async.cg.shared.global [%0], [%1], 16;" :: "r"(dst), "l"(src));
}
#define CP_COMMIT() asm volatile("cp.async.commit_group;" ::: "memory")
#define CP_WAIT0()  asm volatile("cp.async.wait_group 0;" ::: "memory")

// m16n8k8 tf32 mma, D accumulates in place.
// A frag: a0=(g,tig) a1=(g+8,tig) a2=(g,tig+4) a3=(g+8,tig+4)
// B frag: b0=(k=tig,n=g) b1=(k=tig+4,n=g)
// C frag: d0=(g,2tig) d1=(g,2tig+1) d2=(g+8,2tig) d3=(g+8,2tig+1)
__device__ __forceinline__ void mma_tf32(float& d0, float& d1, float& d2, float& d3,
                                         uint32_t a0, uint32_t a1, uint32_t a2, uint32_t a3,
                                         uint32_t b0, uint32_t b1) {
    asm volatile(
        "mma.sync.aligned.m16n8k8.row.col.f32.tf32.tf32.f32 "
        "{%0,%1,%2,%3}, {%4,%5,%6,%7}, {%8,%9}, {%0,%1,%2,%3};"
        : "+f"(d0), "+f"(d1), "+f"(d2), "+f"(d3)
        : "r"(a0), "r"(a1), "r"(a2), "r"(a3), "r"(b0), "r"(b1));
}
__device__ __forceinline__ uint32_t fas(float f) { return __float_as_uint(f); }

// ============================================================================
// Projection: out[m][h] = sum_c x[m][c] W[h][c]
// CTA 64x128, 128 threads, 2x2 warps, BK=32, stride 36. grid (3, 256).
// NEW: cp.async double-buffered staging (raw fp32 in smem, cvt at frag load)
// so LDG latency overlaps compute. Dyn smem 55.3KB, 3 CTA/SM.
// ============================================================================
#define PJ_STR 36
#define PX_FLT (64 * PJ_STR)                   // 2304 floats per x buf
#define PW_FLT (HS * PJ_STR)                   // 4608 floats per W buf
#define PW_OFF (2 * PX_FLT)                    // 4608
#define SM_PROJ ((2 * PX_FLT + 2 * PW_FLT) * 4)  // 55296 bytes

__global__ __launch_bounds__(128, 3)
void proj_kernel(const float* __restrict__ x, const float* __restrict__ Wq,
                 const float* __restrict__ Wk, const float* __restrict__ Wv)
{
    extern __shared__ float psm[];
    const uint32_t sb = smem_u32(psm);

    const int t = threadIdx.x;
    const int w = t >> 5, lane = t & 31;
    const int g = lane >> 2, tig = lane & 3;
    const int pr = w & 1, pc = w >> 1;
    const int wh = blockIdx.x;
    const float* __restrict__ W = (wh == 0) ? Wq : ((wh == 1) ? Wk : Wv);
    float* __restrict__ outg = (wh == 0) ? g_Q : ((wh == 1) ? g_K : g_V);
    const int m0g = blockIdx.y * 64;

    float of[2][8][4];
    #pragma unroll
    for (int mb = 0; mb < 2; mb++)
        #pragma unroll
        for (int nt = 0; nt < 8; nt++)
            #pragma unroll
            for (int e = 0; e < 4; e++) of[mb][nt][e] = 0.0f;

    // prologue: stage tile kc=0 into buf 0
    #pragma unroll
    for (int i = 0; i < 4; i++) {              // x: 64 rows x 8 chunks
        int idx = t + 128 * i;
        int row = idx >> 3, q4 = idx & 7;
        cpa16(sb + (row * PJ_STR + 4 * q4) * 4, &x[(size_t)(m0g + row) * DM + 4 * q4]);
    }
    #pragma unroll
    for (int i = 0; i < 8; i++) {              // W: 128 rows x 8 chunks
        int idx = t + 128 * i;
        int row = idx >> 3, q4 = idx & 7;
        cpa16(sb + (PW_OFF + row * PJ_STR + 4 * q4) * 4, &W[(size_t)row * DM + 4 * q4]);
    }
    CP_COMMIT();

    for (int kc = 0; kc < DM / 32; kc++) {
        CP_WAIT0();
        __syncthreads();                       // tile kc landed; kc-1 reads done

        if (kc < DM / 32 - 1) {                // prefetch kc+1 into other buf
            int buf = (kc + 1) & 1;
            int k0g = (kc + 1) * 32;
            #pragma unroll
            for (int i = 0; i < 4; i++) {
                int idx = t + 128 * i;
                int row = idx >> 3, q4 = idx & 7;
                cpa16(sb + (buf * PX_FLT + row * PJ_STR + 4 * q4) * 4,
                      &x[(size_t)(m0g + row) * DM + k0g + 4 * q4]);
            }
            #pragma unroll
            for (int i = 0; i < 8; i++) {
                int idx = t + 128 * i;
                int row = idx >> 3, q4 = idx & 7;
                cpa16(sb + (PW_OFF + buf * PW_FLT + row * PJ_STR + 4 * q4) * 4,
                      &W[(size_t)row * DM + k0g + 4 * q4]);
            }
        }
        CP_COMMIT();

        const float* xs = psm + (kc & 1) * PX_FLT;
        const float* ws = psm + PW_OFF + (kc & 1) * PW_FLT;

        #pragma unroll
        for (int ks = 0; ks < 4; ks++) {
            int k0 = 8 * ks;
            uint32_t a[2][4];
            #pragma unroll
            for (int mb = 0; mb < 2; mb++) {
                int r0 = 32 * pr + 16 * mb + g;
                a[mb][0] = f2tf(xs[r0 * PJ_STR + k0 + tig]);
                a[mb][1] = f2tf(xs[(r0 + 8) * PJ_STR + k0 + tig]);
                a[mb][2] = f2tf(xs[r0 * PJ_STR + k0 + tig + 4]);
                a[mb][3] = f2tf(xs[(r0 + 8) * PJ_STR + k0 + tig + 4]);
            }
            #pragma unroll
            for (int nt = 0; nt < 8; nt++) {
                int col = 64 * pc + 8 * nt + g;
                uint32_t b0 = f2tf(ws[col * PJ_STR + k0 + tig]);
                uint32_t b1 = f2tf(ws[col * PJ_STR + k0 + tig + 4]);
                #pragma unroll
                for (int mb = 0; mb < 2; mb++)
                    mma_tf32(of[mb][nt][0], of[mb][nt][1], of[mb][nt][2], of[mb][nt][3],
                             a[mb][0], a[mb][1], a[mb][2], a[mb][3], b0, b1);
            }
        }
    }

    const float scale = (wh == 0) ? 0.12751744668f : 1.0f;   // log2(e)/sqrt(128)
    #pragma unroll
    for (int mb = 0; mb < 2; mb++) {
        int r0 = m0g + 32 * pr + 16 * mb + g;
        #pragma unroll
        for (int nt = 0; nt < 8; nt++) {
            int col = 64 * pc + 8 * nt + 2 * tig;
            float2 v0, v1;
            v0.x = __uint_as_float(f2tf(of[mb][nt][0] * scale));
            v0.y = __uint_as_float(f2tf(of[mb][nt][1] * scale));
            v1.x = __uint_as_float(f2tf(of[mb][nt][2] * scale));
            v1.y = __uint_as_float(f2tf(of[mb][nt][3] * scale));
            *(float2*)&outg[(size_t)r0 * HS + col] = v0;
            *(float2*)&outg[(size_t)(r0 + 8) * HS + col] = v1;
        }
    }
}

// ============================================================================
// Causal flash attention (R12 body, unchanged) with heavy/light interleaved
// CTA schedule: even q -> heavy iq (63-q/2), odd q -> light iq ((q-1)/2).
// Wave 1 mixes 19 heaviest + 18 lightest iq's -> makespan ~= 64 tile-units.
// ============================================================================
#define QK_STR 132
#define V_STR  136
#define KS_OFF 0
#define KS_FLT (64 * QK_STR)                 // 8448
#define VS_OFF (2 * KS_FLT)                  // 16896
#define VS_FLT (64 * V_STR)                  // 8704
#define LP_OFF (VS_OFF + 2 * VS_FLT)         // 34304
#define SM_ATTN ((LP_OFF + 128) * 4)         // 137728 bytes
#define PART_STR 132

__global__ __launch_bounds__(256, 1)
void attn_kernel(float* __restrict__ out)
{
    extern __shared__ float sm[];
    const uint32_t sb = smem_u32(sm);
    const int t = threadIdx.x;
    const int w = t >> 5, lane = t & 31;
    const int g = lane >> 2, tig = lane & 3;
    const int wr = w & 3, wc = w >> 2;
    const int m0 = wr * 16;

    const int q = blockIdx.x >> 2;
    const int b = blockIdx.x & 3;
    const int iq = (q & 1) ? ((q - 1) >> 1) : (63 - (q >> 1));   // heavy/light mix
    const int q0 = iq * 64;
    const int qrow = q0 + m0 + g;

    const float* __restrict__ Qg    = g_Q + ((size_t)b * TSEQ + q0) * HS;
    const float* __restrict__ Kbase = g_K + (size_t)b * TSEQ * HS;
    const float* __restrict__ Vbase = g_V + (size_t)b * TSEQ * HS;

    // ---- prologue: K/V tile 0 via cp.async ----
    #pragma unroll
    for (int i = 0; i < 8; i++) {
        int idx = t + 256 * i;
        int row = idx >> 5, q4 = idx & 31;
        cpa16(sb + (KS_OFF + row * QK_STR + 4 * q4) * 4, &Kbase[row * HS + 4 * q4]);
        cpa16(sb + (VS_OFF + row * V_STR + 4 * q4) * 4, &Vbase[row * HS + 4 * q4]);
    }
    CP_COMMIT();

    // Q fragments (loop-invariant, registers)
    uint32_t qa[16][4];
    #pragma unroll
    for (int ks = 0; ks < 16; ks++) {
        int k0 = 8 * ks;
        qa[ks][0] = fas(Qg[(m0 + g) * HS + k0 + tig]);
        qa[ks][1] = fas(Qg[(m0 + g + 8) * HS + k0 + tig]);
        qa[ks][2] = fas(Qg[(m0 + g) * HS + k0 + tig + 4]);
        qa[ks][3] = fas(Qg[(m0 + g + 8) * HS + k0 + tig + 4]);
    }

    float of[16][4];
    #pragma unroll
    for (int nt = 0; nt < 16; nt++)
        #pragma unroll
        for (int e = 0; e < 4; e++) of[nt][e] = 0.0f;
    float lsum0 = 0.0f, lsum1 = 0.0f;

    for (int j = 0; j <= iq; j++) {
        CP_WAIT0();
        __syncthreads();                 // tile j landed; tile j-1 reads done

        if (j < iq) {                    // prefetch j+1 into the other buffer
            int buf = (j + 1) & 1;
            const float* Kg = Kbase + (size_t)(j + 1) * 64 * HS;
            const float* Vg = Vbase + (size_t)(j + 1) * 64 * HS;
            #pragma unroll
            for (int i = 0; i < 8; i++) {
                int idx = t + 256 * i;
                int row = idx >> 5, q4 = idx & 31;
                cpa16(sb + (KS_OFF + buf * KS_FLT + row * QK_STR + 4 * q4) * 4,
                      &Kg[row * HS + 4 * q4]);
                cpa16(sb + (VS_OFF + buf * VS_FLT + row * V_STR + 4 * q4) * 4,
                      &Vg[row * HS + 4 * q4]);
            }
        }
        CP_COMMIT();

        const float* Kb = sm + KS_OFF + (j & 1) * KS_FLT;
        const float* Vb = sm + VS_OFF + (j & 1) * VS_FLT;

        // ---- S = Q K^T : 16 x 32 per warp; B-frags software-pipelined ----
        float sfE[4][4], sfO[4][4];
        #pragma unroll
        for (int nt = 0; nt < 4; nt++)
            #pragma unroll
            for (int e = 0; e < 4; e++) { sfE[nt][e] = 0.0f; sfO[nt][e] = 0.0f; }

        uint32_t bc0[4], bc1[4];
        #pragma unroll
        for (int nt = 0; nt < 4; nt++) {
            int col = 32 * wc + 8 * nt + g;
            bc0[nt] = fas(Kb[col * QK_STR + tig]);
            bc1[nt] = fas(Kb[col * QK_STR + tig + 4]);
        }
        #pragma unroll
        for (int ks = 0; ks < 16; ks++) {
            uint32_t bn0[4], bn1[4];
            if (ks < 15) {
                int k0n = 8 * (ks + 1);
                #pragma unroll
                for (int nt = 0; nt < 4; nt++) {
                    int col = 32 * wc + 8 * nt + g;
                    bn0[nt] = fas(Kb[col * QK_STR + k0n + tig]);
                    bn1[nt] = fas(Kb[col * QK_STR + k0n + tig + 4]);
                }
            }
            #pragma unroll
            for (int nt = 0; nt < 4; nt++) {
                float* sf = (ks & 1) ? sfO[nt] : sfE[nt];
                mma_tf32(sf[0], sf[1], sf[2], sf[3],
                         qa[ks][0], qa[ks][1], qa[ks][2], qa[ks][3],
                         bc0[nt], bc1[nt]);
            }
            if (ks < 15) {
                #pragma unroll
                for (int nt = 0; nt < 4; nt++) { bc0[nt] = bn0[nt]; bc1[nt] = bn1[nt]; }
            }
        }

        // ---- softmax: P = ex2(S) in registers (tf32 bits) ----
        const int jb = j * 64;
        const bool diag = (j == iq);
        uint32_t p[4][4];
        #pragma unroll
        for (int nt = 0; nt < 4; nt++) {
            int coll = 32 * wc + 8 * nt + 2 * tig;
            #pragma unroll
            for (int rr = 0; rr < 2; rr++) {
                float p0 = ex2(sfE[nt][2 * rr + 0] + sfO[nt][2 * rr + 0]);
                float p1 = ex2(sfE[nt][2 * rr + 1] + sfO[nt][2 * rr + 1]);
                int rglob = qrow + 8 * rr;
                if (diag && jb + coll > rglob)     p0 = 0.0f;
                if (diag && jb + coll + 1 > rglob) p1 = 0.0f;
                if (rr == 0) lsum0 += p0 + p1; else lsum1 += p0 + p1;
                p[nt][2 * rr + 0] = f2tf(p0);
                p[nt][2 * rr + 1] = f2tf(p1);
            }
        }

        // ---- O += P V over this warp's 32 keys; A-frags via shfl ----
        const int srcA = 4 * g + (tig >> 1);
        const bool odd = (tig & 1) != 0;
        #pragma unroll
        for (int ks2 = 0; ks2 < 4; ks2++) {
            uint32_t e00 = __shfl_sync(0xffffffffu, p[ks2][0], srcA);
            uint32_t e01 = __shfl_sync(0xffffffffu, p[ks2][1], srcA);
            uint32_t e10 = __shfl_sync(0xffffffffu, p[ks2][2], srcA);
            uint32_t e11 = __shfl_sync(0xffffffffu, p[ks2][3], srcA);
            uint32_t f00 = __shfl_sync(0xffffffffu, p[ks2][0], srcA + 2);
            uint32_t f01 = __shfl_sync(0xffffffffu, p[ks2][1], srcA + 2);
            uint32_t f10 = __shfl_sync(0xffffffffu, p[ks2][2], srcA + 2);
            uint32_t f11 = __shfl_sync(0xffffffffu, p[ks2][3], srcA + 2);
            uint32_t a0 = odd ? e01 : e00;
            uint32_t a1 = odd ? e11 : e10;
            uint32_t a2 = odd ? f01 : f00;
            uint32_t a3 = odd ? f11 : f10;

            const int krow = 32 * wc + 8 * ks2;
            #pragma unroll
            for (int nt2 = 0; nt2 < 16; nt2++) {
                int col = 8 * nt2 + g;
                uint32_t b0 = fas(Vb[(krow + tig) * V_STR + col]);
                uint32_t b1 = fas(Vb[(krow + 4 + tig) * V_STR + col]);
                mma_tf32(of[nt2][0], of[nt2][1], of[nt2][2], of[nt2][3],
                         a0, a1, a2, a3, b0, b1);
            }
        }
    }

    // ---- epilogue: reduce partial O across wc pairs + l, normalize, store ----
    lsum0 += __shfl_xor_sync(0xffffffffu, lsum0, 1);
    lsum0 += __shfl_xor_sync(0xffffffffu, lsum0, 2);
    lsum1 += __shfl_xor_sync(0xffffffffu, lsum1, 1);
    lsum1 += __shfl_xor_sync(0xffffffffu, lsum1, 2);

    __syncthreads();
    float* part = sm + KS_OFF;
    float* Lp = sm + LP_OFF;
    {
        float* pw = part + wc * (64 * PART_STR);
        #pragma unroll
        for (int nt2 = 0; nt2 < 16; nt2++) {
            int col = 8 * nt2 + 2 * tig;
            *(float2*)&pw[(m0 + g) * PART_STR + col] =
                make_float2(of[nt2][0], of[nt2][1]);
            *(float2*)&pw[(m0 + g + 8) * PART_STR + col] =
                make_float2(of[nt2][2], of[nt2][3]);
        }
        if (tig == 0) {
            Lp[wc * 64 + m0 + g] = lsum0;
            Lp[wc * 64 + m0 + g + 8] = lsum1;
        }
    }
    __syncthreads();

    const float inv0 = 1.0f / (Lp[m0 + g] + Lp[64 + m0 + g]);
    const float inv1 = 1.0f / (Lp[m0 + g + 8] + Lp[64 + m0 + g + 8]);

    float* __restrict__ o0 = out + ((size_t)b * TSEQ + qrow) * HS;
    float* __restrict__ o1 = out + ((size_t)b * TSEQ + qrow + 8) * HS;
    #pragma unroll
    for (int nt = 0; nt < 8; nt++) {
        int col = 64 * wc + 8 * nt + 2 * tig;
        float2 s0a = *(float2*)&part[(m0 + g) * PART_STR + col];
        float2 s0b = *(float2*)&part[64 * PART_STR + (m0 + g) * PART_STR + col];
        float2 s1a = *(float2*)&part[(m0 + g + 8) * PART_STR + col];
        float2 s1b = *(float2*)&part[64 * PART_STR + (m0 + g + 8) * PART_STR + col];
        float2 v0 = make_float2((s0a.x + s0b.x) * inv0, (s0a.y + s0b.y) * inv0);
        float2 v1 = make_float2((s1a.x + s1b.x) * inv1, (s1a.y + s1b.y) * inv1);
        *(float2*)&o0[col] = v0;
        *(float2*)&o1[col] = v1;
    }
}

extern "C" void kernel_launch(void* const* d_in, const int* in_sizes, int n_in,
                              void* d_out, int out_size)
{
    const float* x  = (const float*)d_in[0];
    const float* Wq = (const float*)d_in[1];
    const float* Wk = (const float*)d_in[2];
    const float* Wv = (const float*)d_in[3];
    float* out = (float*)d_out;

    cudaFuncSetAttribute(proj_kernel, cudaFuncAttributeMaxDynamicSharedMemorySize, SM_PROJ);
    cudaFuncSetAttribute(attn_kernel, cudaFuncAttributeMaxDynamicSharedMemorySize, SM_ATTN);

    proj_kernel<<<dim3(3, NROWS / 64), 128, SM_PROJ>>>(x, Wq, Wk, Wv);
    attn_kernel<<<(TSEQ / 64) * BATCH, 256, SM_ATTN>>>(out);
}

// round 14
// speedup vs baseline: 1.1158x; 1.1158x over previous
#include <cuda_runtime.h>
#include <cstdint>

#define BATCH 4
#define TSEQ  4096
#define DM    1024
#define HS    128
#define NROWS (BATCH*TSEQ)

// Scratch (cudaMalloc forbidden). Q pre-scaled by log2(e)/sqrt(128) so softmax
// is a bare ex2; Q/K/V all tf32-rounded at projection epilogue.
__device__ float g_Q[NROWS * HS];
__device__ float g_K[NROWS * HS];
__device__ float g_V[NROWS * HS];

__device__ __forceinline__ uint32_t f2tf(float f) {
    uint32_t u; asm("cvt.rna.tf32.f32 %0, %1;" : "=r"(u) : "f"(f)); return u;
}
__device__ __forceinline__ float ex2(float x) {
    float y; asm("ex2.approx.f32 %0, %1;" : "=f"(y) : "f"(x)); return y;
}
__device__ __forceinline__ uint32_t smem_u32(const void* p) {
    uint32_t a; asm("{ .reg .u64 t; cvta.to.shared.u64 t, %1; cvt.u32.u64 %0, t; }" : "=r"(a) : "l"(p));
    return a;
}
__device__ __forceinline__ void cpa16(uint32_t dst, const void* src) {
    asm volatile("cp.async.cg.shared.global [%0], [%1], 16;" :: "r"(dst), "l"(src));
}
#define CP_COMMIT() asm volatile("cp.async.commit_group;" ::: "memory")
#define CP_WAIT0()  asm volatile("cp.async.wait_group 0;" ::: "memory")

// m16n8k8 tf32 mma, D accumulates in place.
// A frag: a0=(g,tig) a1=(g+8,tig) a2=(g,tig+4) a3=(g+8,tig+4)
// B frag: b0=(k=tig,n=g) b1=(k=tig+4,n=g)
// C frag: d0=(g,2tig) d1=(g,2tig+1) d2=(g+8,2tig) d3=(g+8,2tig+1)
__device__ __forceinline__ void mma_tf32(float& d0, float& d1, float& d2, float& d3,
                                         uint32_t a0, uint32_t a1, uint32_t a2, uint32_t a3,
                                         uint32_t b0, uint32_t b1) {
    asm volatile(
        "mma.sync.aligned.m16n8k8.row.col.f32.tf32.tf32.f32 "
        "{%0,%1,%2,%3}, {%4,%5,%6,%7}, {%8,%9}, {%0,%1,%2,%3};"
        : "+f"(d0), "+f"(d1), "+f"(d2), "+f"(d3)
        : "r"(a0), "r"(a1), "r"(a2), "r"(a3), "r"(b0), "r"(b1));
}
__device__ __forceinline__ uint32_t fas(float f) { return __float_as_uint(f); }

// ============================================================================
// Projection (R13 cp.async version, measured 109.9us): out = x W^T
// CTA 64x128, 128 threads, 2x2 warps, BK=32, stride 36. grid (3, 256).
// cp.async double-buffered staging; cvt at fragment load. 3 CTA/SM.
// ============================================================================
#define PJ_STR 36
#define PX_FLT (64 * PJ_STR)
#define PW_FLT (HS * PJ_STR)
#define PW_OFF (2 * PX_FLT)
#define SM_PROJ ((2 * PX_FLT + 2 * PW_FLT) * 4)

__global__ __launch_bounds__(128, 3)
void proj_kernel(const float* __restrict__ x, const float* __restrict__ Wq,
                 const float* __restrict__ Wk, const float* __restrict__ Wv)
{
    extern __shared__ float psm[];
    const uint32_t sb = smem_u32(psm);

    const int t = threadIdx.x;
    const int w = t >> 5, lane = t & 31;
    const int g = lane >> 2, tig = lane & 3;
    const int pr = w & 1, pc = w >> 1;
    const int wh = blockIdx.x;
    const float* __restrict__ W = (wh == 0) ? Wq : ((wh == 1) ? Wk : Wv);
    float* __restrict__ outg = (wh == 0) ? g_Q : ((wh == 1) ? g_K : g_V);
    const int m0g = blockIdx.y * 64;

    float of[2][8][4];
    #pragma unroll
    for (int mb = 0; mb < 2; mb++)
        #pragma unroll
        for (int nt = 0; nt < 8; nt++)
            #pragma unroll
            for (int e = 0; e < 4; e++) of[mb][nt][e] = 0.0f;

    #pragma unroll
    for (int i = 0; i < 4; i++) {
        int idx = t + 128 * i;
        int row = idx >> 3, q4 = idx & 7;
        cpa16(sb + (row * PJ_STR + 4 * q4) * 4, &x[(size_t)(m0g + row) * DM + 4 * q4]);
    }
    #pragma unroll
    for (int i = 0; i < 8; i++) {
        int idx = t + 128 * i;
        int row = idx >> 3, q4 = idx & 7;
        cpa16(sb + (PW_OFF + row * PJ_STR + 4 * q4) * 4, &W[(size_t)row * DM + 4 * q4]);
    }
    CP_COMMIT();

    for (int kc = 0; kc < DM / 32; kc++) {
        CP_WAIT0();
        __syncthreads();

        if (kc < DM / 32 - 1) {
            int buf = (kc + 1) & 1;
            int k0g = (kc + 1) * 32;
            #pragma unroll
            for (int i = 0; i < 4; i++) {
                int idx = t + 128 * i;
                int row = idx >> 3, q4 = idx & 7;
                cpa16(sb + (buf * PX_FLT + row * PJ_STR + 4 * q4) * 4,
                      &x[(size_t)(m0g + row) * DM + k0g + 4 * q4]);
            }
            #pragma unroll
            for (int i = 0; i < 8; i++) {
                int idx = t + 128 * i;
                int row = idx >> 3, q4 = idx & 7;
                cpa16(sb + (PW_OFF + buf * PW_FLT + row * PJ_STR + 4 * q4) * 4,
                      &W[(size_t)row * DM + k0g + 4 * q4]);
            }
        }
        CP_COMMIT();

        const float* xs = psm + (kc & 1) * PX_FLT;
        const float* ws = psm + PW_OFF + (kc & 1) * PW_FLT;

        #pragma unroll
        for (int ks = 0; ks < 4; ks++) {
            int k0 = 8 * ks;
            uint32_t a[2][4];
            #pragma unroll
            for (int mb = 0; mb < 2; mb++) {
                int r0 = 32 * pr + 16 * mb + g;
                a[mb][0] = f2tf(xs[r0 * PJ_STR + k0 + tig]);
                a[mb][1] = f2tf(xs[(r0 + 8) * PJ_STR + k0 + tig]);
                a[mb][2] = f2tf(xs[r0 * PJ_STR + k0 + tig + 4]);
                a[mb][3] = f2tf(xs[(r0 + 8) * PJ_STR + k0 + tig + 4]);
            }
            #pragma unroll
            for (int nt = 0; nt < 8; nt++) {
                int col = 64 * pc + 8 * nt + g;
                uint32_t b0 = f2tf(ws[col * PJ_STR + k0 + tig]);
                uint32_t b1 = f2tf(ws[col * PJ_STR + k0 + tig + 4]);
                #pragma unroll
                for (int mb = 0; mb < 2; mb++)
                    mma_tf32(of[mb][nt][0], of[mb][nt][1], of[mb][nt][2], of[mb][nt][3],
                             a[mb][0], a[mb][1], a[mb][2], a[mb][3], b0, b1);
            }
        }
    }

    const float scale = (wh == 0) ? 0.12751744668f : 1.0f;   // log2(e)/sqrt(128)
    #pragma unroll
    for (int mb = 0; mb < 2; mb++) {
        int r0 = m0g + 32 * pr + 16 * mb + g;
        #pragma unroll
        for (int nt = 0; nt < 8; nt++) {
            int col = 64 * pc + 8 * nt + 2 * tig;
            float2 v0, v1;
            v0.x = __uint_as_float(f2tf(of[mb][nt][0] * scale));
            v0.y = __uint_as_float(f2tf(of[mb][nt][1] * scale));
            v1.x = __uint_as_float(f2tf(of[mb][nt][2] * scale));
            v1.y = __uint_as_float(f2tf(of[mb][nt][3] * scale));
            *(float2*)&outg[(size_t)r0 * HS + col] = v0;
            *(float2*)&outg[(size_t)(r0 + 8) * HS + col] = v1;
        }
    }
}

// ============================================================================
// Causal flash attention — EXACT R12 configuration (measured 158.9us):
// heavy-first (LPT) schedule, P in registers via shfl, PV k-split by wc,
// 1 syncthreads per tile, cp.async double-buffered K/V.
// 256 threads: (wr 0..3: 16-row) x (wc 0..1: 32-key window).
// ============================================================================
#define QK_STR 132
#define V_STR  136
#define KS_OFF 0
#define KS_FLT (64 * QK_STR)
#define VS_OFF (2 * KS_FLT)
#define VS_FLT (64 * V_STR)
#define LP_OFF (VS_OFF + 2 * VS_FLT)
#define SM_ATTN ((LP_OFF + 128) * 4)
#define PART_STR 132

__global__ __launch_bounds__(256, 1)
void attn_kernel(float* __restrict__ out)
{
    extern __shared__ float sm[];
    const uint32_t sb = smem_u32(sm);
    const int t = threadIdx.x;
    const int w = t >> 5, lane = t & 31;
    const int g = lane >> 2, tig = lane & 3;
    const int wr = w & 3, wc = w >> 2;
    const int m0 = wr * 16;

    const int b  = blockIdx.x & 3;
    const int iq = (TSEQ / 64 - 1) - (blockIdx.x >> 2);   // heavy first (LPT)
    const int q0 = iq * 64;
    const int qrow = q0 + m0 + g;

    const float* __restrict__ Qg    = g_Q + ((size_t)b * TSEQ + q0) * HS;
    const float* __restrict__ Kbase = g_K + (size_t)b * TSEQ * HS;
    const float* __restrict__ Vbase = g_V + (size_t)b * TSEQ * HS;

    // ---- prologue: K/V tile 0 via cp.async ----
    #pragma unroll
    for (int i = 0; i < 8; i++) {
        int idx = t + 256 * i;
        int row = idx >> 5, q4 = idx & 31;
        cpa16(sb + (KS_OFF + row * QK_STR + 4 * q4) * 4, &Kbase[row * HS + 4 * q4]);
        cpa16(sb + (VS_OFF + row * V_STR + 4 * q4) * 4, &Vbase[row * HS + 4 * q4]);
    }
    CP_COMMIT();

    // Q fragments (loop-invariant, registers)
    uint32_t qa[16][4];
    #pragma unroll
    for (int ks = 0; ks < 16; ks++) {
        int k0 = 8 * ks;
        qa[ks][0] = fas(Qg[(m0 + g) * HS + k0 + tig]);
        qa[ks][1] = fas(Qg[(m0 + g + 8) * HS + k0 + tig]);
        qa[ks][2] = fas(Qg[(m0 + g) * HS + k0 + tig + 4]);
        qa[ks][3] = fas(Qg[(m0 + g + 8) * HS + k0 + tig + 4]);
    }

    float of[16][4];
    #pragma unroll
    for (int nt = 0; nt < 16; nt++)
        #pragma unroll
        for (int e = 0; e < 4; e++) of[nt][e] = 0.0f;
    float lsum0 = 0.0f, lsum1 = 0.0f;

    for (int j = 0; j <= iq; j++) {
        CP_WAIT0();
        __syncthreads();                 // tile j landed; tile j-1 reads done

        if (j < iq) {                    // prefetch j+1 into the other buffer
            int buf = (j + 1) & 1;
            const float* Kg = Kbase + (size_t)(j + 1) * 64 * HS;
            const float* Vg = Vbase + (size_t)(j + 1) * 64 * HS;
            #pragma unroll
            for (int i = 0; i < 8; i++) {
                int idx = t + 256 * i;
                int row = idx >> 5, q4 = idx & 31;
                cpa16(sb + (KS_OFF + buf * KS_FLT + row * QK_STR + 4 * q4) * 4,
                      &Kg[row * HS + 4 * q4]);
                cpa16(sb + (VS_OFF + buf * VS_FLT + row * V_STR + 4 * q4) * 4,
                      &Vg[row * HS + 4 * q4]);
            }
        }
        CP_COMMIT();

        const float* Kb = sm + KS_OFF + (j & 1) * KS_FLT;
        const float* Vb = sm + VS_OFF + (j & 1) * VS_FLT;

        // ---- S = Q K^T : 16 x 32 per warp; B-frags software-pipelined ----
        float sfE[4][4], sfO[4][4];
        #pragma unroll
        for (int nt = 0; nt < 4; nt++)
            #pragma unroll
            for (int e = 0; e < 4; e++) { sfE[nt][e] = 0.0f; sfO[nt][e] = 0.0f; }

        uint32_t bc0[4], bc1[4];
        #pragma unroll
        for (int nt = 0; nt < 4; nt++) {
            int col = 32 * wc + 8 * nt + g;
            bc0[nt] = fas(Kb[col * QK_STR + tig]);
            bc1[nt] = fas(Kb[col * QK_STR + tig + 4]);
        }
        #pragma unroll
        for (int ks = 0; ks < 16; ks++) {
            uint32_t bn0[4], bn1[4];
            if (ks < 15) {
                int k0n = 8 * (ks + 1);
                #pragma unroll
                for (int nt = 0; nt < 4; nt++) {
                    int col = 32 * wc + 8 * nt + g;
                    bn0[nt] = fas(Kb[col * QK_STR + k0n + tig]);
                    bn1[nt] = fas(Kb[col * QK_STR + k0n + tig + 4]);
                }
            }
            #pragma unroll
            for (int nt = 0; nt < 4; nt++) {
                float* sf = (ks & 1) ? sfO[nt] : sfE[nt];
                mma_tf32(sf[0], sf[1], sf[2], sf[3],
                         qa[ks][0], qa[ks][1], qa[ks][2], qa[ks][3],
                         bc0[nt], bc1[nt]);
            }
            if (ks < 15) {
                #pragma unroll
                for (int nt = 0; nt < 4; nt++) { bc0[nt] = bn0[nt]; bc1[nt] = bn1[nt]; }
            }
        }

        // ---- softmax: P = ex2(S) in registers (tf32 bits) ----
        const int jb = j * 64;
        const bool diag = (j == iq);
        uint32_t p[4][4];
        #pragma unroll
        for (int nt = 0; nt < 4; nt++) {
            int coll = 32 * wc + 8 * nt + 2 * tig;
            #pragma unroll
            for (int rr = 0; rr < 2; rr++) {
                float p0 = ex2(sfE[nt][2 * rr + 0] + sfO[nt][2 * rr + 0]);
                float p1 = ex2(sfE[nt][2 * rr + 1] + sfO[nt][2 * rr + 1]);
                int rglob = qrow + 8 * rr;
                if (diag && jb + coll > rglob)     p0 = 0.0f;
                if (diag && jb + coll + 1 > rglob) p1 = 0.0f;
                if (rr == 0) lsum0 += p0 + p1; else lsum1 += p0 + p1;
                p[nt][2 * rr + 0] = f2tf(p0);
                p[nt][2 * rr + 1] = f2tf(p1);
            }
        }

        // ---- O += P V over this warp's 32 keys; A-frags via shfl ----
        const int srcA = 4 * g + (tig >> 1);
        const bool odd = (tig & 1) != 0;
        #pragma unroll
        for (int ks2 = 0; ks2 < 4; ks2++) {
            uint32_t e00 = __shfl_sync(0xffffffffu, p[ks2][0], srcA);
            uint32_t e01 = __shfl_sync(0xffffffffu, p[ks2][1], srcA);
            uint32_t e10 = __shfl_sync(0xffffffffu, p[ks2][2], srcA);
            uint32_t e11 = __shfl_sync(0xffffffffu, p[ks2][3], srcA);
            uint32_t f00 = __shfl_sync(0xffffffffu, p[ks2][0], srcA + 2);
            uint32_t f01 = __shfl_sync(0xffffffffu, p[ks2][1], srcA + 2);
            uint32_t f10 = __shfl_sync(0xffffffffu, p[ks2][2], srcA + 2);
            uint32_t f11 = __shfl_sync(0xffffffffu, p[ks2][3], srcA + 2);
            uint32_t a0 = odd ? e01 : e00;
            uint32_t a1 = odd ? e11 : e10;
            uint32_t a2 = odd ? f01 : f00;
            uint32_t a3 = odd ? f11 : f10;

            const int krow = 32 * wc + 8 * ks2;
            #pragma unroll
            for (int nt2 = 0; nt2 < 16; nt2++) {
                int col = 8 * nt2 + g;
                uint32_t b0 = fas(Vb[(krow + tig) * V_STR + col]);
                uint32_t b1 = fas(Vb[(krow + 4 + tig) * V_STR + col]);
                mma_tf32(of[nt2][0], of[nt2][1], of[nt2][2], of[nt2][3],
                         a0, a1, a2, a3, b0, b1);
            }
        }
    }

    // ---- epilogue: reduce partial O across wc pairs + l, normalize, store ----
    lsum0 += __shfl_xor_sync(0xffffffffu, lsum0, 1);
    lsum0 += __shfl_xor_sync(0xffffffffu, lsum0, 2);
    lsum1 += __shfl_xor_sync(0xffffffffu, lsum1, 1);
    lsum1 += __shfl_xor_sync(0xffffffffu, lsum1, 2);

    __syncthreads();
    float* part = sm + KS_OFF;
    float* Lp = sm + LP_OFF;
    {
        float* pw = part + wc * (64 * PART_STR);
        #pragma unroll
        for (int nt2 = 0; nt2 < 16; nt2++) {
            int col = 8 * nt2 + 2 * tig;
            *(float2*)&pw[(m0 + g) * PART_STR + col] =
                make_float2(of[nt2][0], of[nt2][1]);
            *(float2*)&pw[(m0 + g + 8) * PART_STR + col] =
                make_float2(of[nt2][2], of[nt2][3]);
        }
        if (tig == 0) {
            Lp[wc * 64 + m0 + g] = lsum0;
            Lp[wc * 64 + m0 + g + 8] = lsum1;
        }
    }
    __syncthreads();

    const float inv0 = 1.0f / (Lp[m0 + g] + Lp[64 + m0 + g]);
    const float inv1 = 1.0f / (Lp[m0 + g + 8] + Lp[64 + m0 + g + 8]);

    float* __restrict__ o0 = out + ((size_t)b * TSEQ + qrow) * HS;
    float* __restrict__ o1 = out + ((size_t)b * TSEQ + qrow + 8) * HS;
    #pragma unroll
    for (int nt = 0; nt < 8; nt++) {
        int col = 64 * wc + 8 * nt + 2 * tig;
        float2 s0a = *(float2*)&part[(m0 + g) * PART_STR + col];
        float2 s0b = *(float2*)&part[64 * PART_STR + (m0 + g) * PART_STR + col];
        float2 s1a = *(float2*)&part[(m0 + g + 8) * PART_STR + col];
        float2 s1b = *(float2*)&part[64 * PART_STR + (m0 + g + 8) * PART_STR + col];
        float2 v0 = make_float2((s0a.x + s0b.x) * inv0, (s0a.y + s0b.y) * inv0);
        float2 v1 = make_float2((s1a.x + s1b.x) * inv1, (s1a.y + s1b.y) * inv1);
        *(float2*)&o0[col] = v0;
        *(float2*)&o1[col] = v1;
    }
}

extern "C" void kernel_launch(void* const* d_in, const int* in_sizes, int n_in,
                              void* d_out, int out_size)
{
    const float* x  = (const float*)d_in[0];
    const float* Wq = (const float*)d_in[1];
    const float* Wk = (const float*)d_in[2];
    const float* Wv = (const float*)d_in[3];
    float* out = (float*)d_out;

    cudaFuncSetAttribute(proj_kernel, cudaFuncAttributeMaxDynamicSharedMemorySize, SM_PROJ);
    cudaFuncSetAttribute(attn_kernel, cudaFuncAttributeMaxDynamicSharedMemorySize, SM_ATTN);

    proj_kernel<<<dim3(3, NROWS / 64), 128, SM_PROJ>>>(x, Wq, Wk, Wv);
    attn_kernel<<<(TSEQ / 64) * BATCH, 256, SM_ATTN>>>(out);
}

// round 15
// speedup vs baseline: 1.1413x; 1.0228x over previous
#include <cuda_runtime.h>
#include <cstdint>

#define BATCH 4
#define TSEQ  4096
#define DM    1024
#define HS    128
#define NROWS (BATCH*TSEQ)

// Scratch (cudaMalloc forbidden). Q pre-scaled by log2(e)/sqrt(128) so softmax
// is a bare ex2; Q/K/V all tf32-rounded at projection epilogue.
__device__ float g_Q[NROWS * HS];
__device__ float g_K[NROWS * HS];
__device__ float g_V[NROWS * HS];
// Split-K partials: exp-only softmax -> O and l are purely additive.
__device__ float g_Op[2][NROWS * HS];
__device__ float g_lp[2][NROWS];

__device__ __forceinline__ uint32_t f2tf(float f) {
    uint32_t u; asm("cvt.rna.tf32.f32 %0, %1;" : "=r"(u) : "f"(f)); return u;
}
__device__ __forceinline__ float ex2(float x) {
    float y; asm("ex2.approx.f32 %0, %1;" : "=f"(y) : "f"(x)); return y;
}
__device__ __forceinline__ uint32_t smem_u32(const void* p) {
    uint32_t a; asm("{ .reg .u64 t; cvta.to.shared.u64 t, %1; cvt.u32.u64 %0, t; }" : "=r"(a) : "l"(p));
    return a;
}
__device__ __forceinline__ void cpa16(uint32_t dst, const void* src) {
    asm volatile("cp.async.cg.shared.global [%0], [%1], 16;" :: "r"(dst), "l"(src));
}
#define CP_COMMIT() asm volatile("cp.async.commit_group;" ::: "memory")
#define CP_WAIT0()  asm volatile("cp.async.wait_group 0;" ::: "memory")

// m16n8k8 tf32 mma, D accumulates in place.
__device__ __forceinline__ void mma_tf32(float& d0, float& d1, float& d2, float& d3,
                                         uint32_t a0, uint32_t a1, uint32_t a2, uint32_t a3,
                                         uint32_t b0, uint32_t b1) {
    asm volatile(
        "mma.sync.aligned.m16n8k8.row.col.f32.tf32.tf32.f32 "
        "{%0,%1,%2,%3}, {%4,%5,%6,%7}, {%8,%9}, {%0,%1,%2,%3};"
        : "+f"(d0), "+f"(d1), "+f"(d2), "+f"(d3)
        : "r"(a0), "r"(a1), "r"(a2), "r"(a3), "r"(b0), "r"(b1));
}
__device__ __forceinline__ uint32_t fas(float f) { return __float_as_uint(f); }

// ============================================================================
// Projection (measured-best R13 cp.async version): out = x W^T
// ============================================================================
#define PJ_STR 36
#define PX_FLT (64 * PJ_STR)
#define PW_FLT (HS * PJ_STR)
#define PW_OFF (2 * PX_FLT)
#define SM_PROJ ((2 * PX_FLT + 2 * PW_FLT) * 4)

__global__ __launch_bounds__(128, 3)
void proj_kernel(const float* __restrict__ x, const float* __restrict__ Wq,
                 const float* __restrict__ Wk, const float* __restrict__ Wv)
{
    extern __shared__ float psm[];
    const uint32_t sb = smem_u32(psm);

    const int t = threadIdx.x;
    const int w = t >> 5, lane = t & 31;
    const int g = lane >> 2, tig = lane & 3;
    const int pr = w & 1, pc = w >> 1;
    const int wh = blockIdx.x;
    const float* __restrict__ W = (wh == 0) ? Wq : ((wh == 1) ? Wk : Wv);
    float* __restrict__ outg = (wh == 0) ? g_Q : ((wh == 1) ? g_K : g_V);
    const int m0g = blockIdx.y * 64;

    float of[2][8][4];
    #pragma unroll
    for (int mb = 0; mb < 2; mb++)
        #pragma unroll
        for (int nt = 0; nt < 8; nt++)
            #pragma unroll
            for (int e = 0; e < 4; e++) of[mb][nt][e] = 0.0f;

    #pragma unroll
    for (int i = 0; i < 4; i++) {
        int idx = t + 128 * i;
        int row = idx >> 3, q4 = idx & 7;
        cpa16(sb + (row * PJ_STR + 4 * q4) * 4, &x[(size_t)(m0g + row) * DM + 4 * q4]);
    }
    #pragma unroll
    for (int i = 0; i < 8; i++) {
        int idx = t + 128 * i;
        int row = idx >> 3, q4 = idx & 7;
        cpa16(sb + (PW_OFF + row * PJ_STR + 4 * q4) * 4, &W[(size_t)row * DM + 4 * q4]);
    }
    CP_COMMIT();

    for (int kc = 0; kc < DM / 32; kc++) {
        CP_WAIT0();
        __syncthreads();

        if (kc < DM / 32 - 1) {
            int buf = (kc + 1) & 1;
            int k0g = (kc + 1) * 32;
            #pragma unroll
            for (int i = 0; i < 4; i++) {
                int idx = t + 128 * i;
                int row = idx >> 3, q4 = idx & 7;
                cpa16(sb + (buf * PX_FLT + row * PJ_STR + 4 * q4) * 4,
                      &x[(size_t)(m0g + row) * DM + k0g + 4 * q4]);
            }
            #pragma unroll
            for (int i = 0; i < 8; i++) {
                int idx = t + 128 * i;
                int row = idx >> 3, q4 = idx & 7;
                cpa16(sb + (PW_OFF + buf * PW_FLT + row * PJ_STR + 4 * q4) * 4,
                      &W[(size_t)row * DM + k0g + 4 * q4]);
            }
        }
        CP_COMMIT();

        const float* xs = psm + (kc & 1) * PX_FLT;
        const float* ws = psm + PW_OFF + (kc & 1) * PW_FLT;

        #pragma unroll
        for (int ks = 0; ks < 4; ks++) {
            int k0 = 8 * ks;
            uint32_t a[2][4];
            #pragma unroll
            for (int mb = 0; mb < 2; mb++) {
                int r0 = 32 * pr + 16 * mb + g;
                a[mb][0] = f2tf(xs[r0 * PJ_STR + k0 + tig]);
                a[mb][1] = f2tf(xs[(r0 + 8) * PJ_STR + k0 + tig]);
                a[mb][2] = f2tf(xs[r0 * PJ_STR + k0 + tig + 4]);
                a[mb][3] = f2tf(xs[(r0 + 8) * PJ_STR + k0 + tig + 4]);
            }
            #pragma unroll
            for (int nt = 0; nt < 8; nt++) {
                int col = 64 * pc + 8 * nt + g;
                uint32_t b0 = f2tf(ws[col * PJ_STR + k0 + tig]);
                uint32_t b1 = f2tf(ws[col * PJ_STR + k0 + tig + 4]);
                #pragma unroll
                for (int mb = 0; mb < 2; mb++)
                    mma_tf32(of[mb][nt][0], of[mb][nt][1], of[mb][nt][2], of[mb][nt][3],
                             a[mb][0], a[mb][1], a[mb][2], a[mb][3], b0, b1);
            }
        }
    }

    const float scale = (wh == 0) ? 0.12751744668f : 1.0f;   // log2(e)/sqrt(128)
    #pragma unroll
    for (int mb = 0; mb < 2; mb++) {
        int r0 = m0g + 32 * pr + 16 * mb + g;
        #pragma unroll
        for (int nt = 0; nt < 8; nt++) {
            int col = 64 * pc + 8 * nt + 2 * tig;
            float2 v0, v1;
            v0.x = __uint_as_float(f2tf(of[mb][nt][0] * scale));
            v0.y = __uint_as_float(f2tf(of[mb][nt][1] * scale));
            v1.x = __uint_as_float(f2tf(of[mb][nt][2] * scale));
            v1.y = __uint_as_float(f2tf(of[mb][nt][3] * scale));
            *(float2*)&outg[(size_t)r0 * HS + col] = v0;
            *(float2*)&outg[(size_t)(r0 + 8) * HS + col] = v1;
        }
    }
}

// ============================================================================
// Causal flash attention, SPLIT-K over keys (R12 body otherwise).
// grid 512 = (32 iq-levels heavy-first) x (4 batches) x (2 key-halves)... full
// mapping: iq = 63-(bx>>3), b = (bx>>1)&3, half = bx&1.
// Half 0: j in [0, ceil(nj/2)); half 1: rest (holds diag). Partials additive
// (exp-only softmax): O and l written raw to g_Op/g_lp; combine normalizes.
// ============================================================================
#define QK_STR 132
#define V_STR  136
#define KS_OFF 0
#define KS_FLT (64 * QK_STR)
#define VS_OFF (2 * KS_FLT)
#define VS_FLT (64 * V_STR)
#define LP_OFF (VS_OFF + 2 * VS_FLT)
#define SM_ATTN ((LP_OFF + 128) * 4)
#define PART_STR 132

__global__ __launch_bounds__(256, 1)
void attn_kernel()
{
    extern __shared__ float sm[];
    const uint32_t sb = smem_u32(sm);
    const int t = threadIdx.x;
    const int w = t >> 5, lane = t & 31;
    const int g = lane >> 2, tig = lane & 3;
    const int wr = w & 3, wc = w >> 2;
    const int m0 = wr * 16;

    const int bx = blockIdx.x;
    const int iq = (TSEQ / 64 - 1) - (bx >> 3);          // heavy first
    const int b = (bx >> 1) & 3;
    const int half = bx & 1;
    const int nj = iq + 1;
    const int h0 = (nj + 1) >> 1;
    const int j0 = half ? h0 : 0;
    const int j1 = half ? nj : h0;
    const int q0 = iq * 64;
    const int qrow = q0 + m0 + g;

    const float* __restrict__ Qg    = g_Q + ((size_t)b * TSEQ + q0) * HS;
    const float* __restrict__ Kbase = g_K + (size_t)b * TSEQ * HS;
    const float* __restrict__ Vbase = g_V + (size_t)b * TSEQ * HS;

    float of[16][4];
    #pragma unroll
    for (int nt = 0; nt < 16; nt++)
        #pragma unroll
        for (int e = 0; e < 4; e++) of[nt][e] = 0.0f;
    float lsum0 = 0.0f, lsum1 = 0.0f;

    if (j0 < j1) {
        // ---- prologue: K/V tile j0 via cp.async ----
        {
            const float* Kg = Kbase + (size_t)j0 * 64 * HS;
            const float* Vg = Vbase + (size_t)j0 * 64 * HS;
            uint32_t kdst = sb + (KS_OFF + (j0 & 1) * KS_FLT) * 4;
            uint32_t vdst = sb + (VS_OFF + (j0 & 1) * VS_FLT) * 4;
            #pragma unroll
            for (int i = 0; i < 8; i++) {
                int idx = t + 256 * i;
                int row = idx >> 5, q4 = idx & 31;
                cpa16(kdst + (row * QK_STR + 4 * q4) * 4, &Kg[row * HS + 4 * q4]);
                cpa16(vdst + (row * V_STR + 4 * q4) * 4, &Vg[row * HS + 4 * q4]);
            }
        }
        CP_COMMIT();

        // Q fragments (loop-invariant, registers)
        uint32_t qa[16][4];
        #pragma unroll
        for (int ks = 0; ks < 16; ks++) {
            int k0 = 8 * ks;
            qa[ks][0] = fas(Qg[(m0 + g) * HS + k0 + tig]);
            qa[ks][1] = fas(Qg[(m0 + g + 8) * HS + k0 + tig]);
            qa[ks][2] = fas(Qg[(m0 + g) * HS + k0 + tig + 4]);
            qa[ks][3] = fas(Qg[(m0 + g + 8) * HS + k0 + tig + 4]);
        }

        for (int j = j0; j < j1; j++) {
            CP_WAIT0();
            __syncthreads();                 // tile j landed; tile j-1 reads done

            if (j + 1 < j1) {                // prefetch j+1 into the other buffer
                int buf = (j + 1) & 1;
                const float* Kg = Kbase + (size_t)(j + 1) * 64 * HS;
                const float* Vg = Vbase + (size_t)(j + 1) * 64 * HS;
                #pragma unroll
                for (int i = 0; i < 8; i++) {
                    int idx = t + 256 * i;
                    int row = idx >> 5, q4 = idx & 31;
                    cpa16(sb + (KS_OFF + buf * KS_FLT + row * QK_STR + 4 * q4) * 4,
                          &Kg[row * HS + 4 * q4]);
                    cpa16(sb + (VS_OFF + buf * VS_FLT + row * V_STR + 4 * q4) * 4,
                          &Vg[row * HS + 4 * q4]);
                }
            }
            CP_COMMIT();

            const float* Kb = sm + KS_OFF + (j & 1) * KS_FLT;
            const float* Vb = sm + VS_OFF + (j & 1) * VS_FLT;

            // ---- S = Q K^T : 16 x 32 per warp; B-frags software-pipelined ----
            float sfE[4][4], sfO[4][4];
            #pragma unroll
            for (int nt = 0; nt < 4; nt++)
                #pragma unroll
                for (int e = 0; e < 4; e++) { sfE[nt][e] = 0.0f; sfO[nt][e] = 0.0f; }

            uint32_t bc0[4], bc1[4];
            #pragma unroll
            for (int nt = 0; nt < 4; nt++) {
                int col = 32 * wc + 8 * nt + g;
                bc0[nt] = fas(Kb[col * QK_STR + tig]);
                bc1[nt] = fas(Kb[col * QK_STR + tig + 4]);
            }
            #pragma unroll
            for (int ks = 0; ks < 16; ks++) {
                uint32_t bn0[4], bn1[4];
                if (ks < 15) {
                    int k0n = 8 * (ks + 1);
                    #pragma unroll
                    for (int nt = 0; nt < 4; nt++) {
                        int col = 32 * wc + 8 * nt + g;
                        bn0[nt] = fas(Kb[col * QK_STR + k0n + tig]);
                        bn1[nt] = fas(Kb[col * QK_STR + k0n + tig + 4]);
                    }
                }
                #pragma unroll
                for (int nt = 0; nt < 4; nt++) {
                    float* sf = (ks & 1) ? sfO[nt] : sfE[nt];
                    mma_tf32(sf[0], sf[1], sf[2], sf[3],
                             qa[ks][0], qa[ks][1], qa[ks][2], qa[ks][3],
                             bc0[nt], bc1[nt]);
                }
                if (ks < 15) {
                    #pragma unroll
                    for (int nt = 0; nt < 4; nt++) { bc0[nt] = bn0[nt]; bc1[nt] = bn1[nt]; }
                }
            }

            // ---- softmax: P = ex2(S) in registers (tf32 bits) ----
            const int jb = j * 64;
            const bool diag = (j == iq);
            uint32_t p[4][4];
            #pragma unroll
            for (int nt = 0; nt < 4; nt++) {
                int coll = 32 * wc + 8 * nt + 2 * tig;
                #pragma unroll
                for (int rr = 0; rr < 2; rr++) {
                    float p0 = ex2(sfE[nt][2 * rr + 0] + sfO[nt][2 * rr + 0]);
                    float p1 = ex2(sfE[nt][2 * rr + 1] + sfO[nt][2 * rr + 1]);
                    int rglob = qrow + 8 * rr;
                    if (diag && jb + coll > rglob)     p0 = 0.0f;
                    if (diag && jb + coll + 1 > rglob) p1 = 0.0f;
                    if (rr == 0) lsum0 += p0 + p1; else lsum1 += p0 + p1;
                    p[nt][2 * rr + 0] = f2tf(p0);
                    p[nt][2 * rr + 1] = f2tf(p1);
                }
            }

            // ---- O += P V over this warp's 32 keys; A-frags via shfl ----
            const int srcA = 4 * g + (tig >> 1);
            const bool odd = (tig & 1) != 0;
            #pragma unroll
            for (int ks2 = 0; ks2 < 4; ks2++) {
                uint32_t e00 = __shfl_sync(0xffffffffu, p[ks2][0], srcA);
                uint32_t e01 = __shfl_sync(0xffffffffu, p[ks2][1], srcA);
                uint32_t e10 = __shfl_sync(0xffffffffu, p[ks2][2], srcA);
                uint32_t e11 = __shfl_sync(0xffffffffu, p[ks2][3], srcA);
                uint32_t f00 = __shfl_sync(0xffffffffu, p[ks2][0], srcA + 2);
                uint32_t f01 = __shfl_sync(0xffffffffu, p[ks2][1], srcA + 2);
                uint32_t f10 = __shfl_sync(0xffffffffu, p[ks2][2], srcA + 2);
                uint32_t f11 = __shfl_sync(0xffffffffu, p[ks2][3], srcA + 2);
                uint32_t a0 = odd ? e01 : e00;
                uint32_t a1 = odd ? e11 : e10;
                uint32_t a2 = odd ? f01 : f00;
                uint32_t a3 = odd ? f11 : f10;

                const int krow = 32 * wc + 8 * ks2;
                #pragma unroll
                for (int nt2 = 0; nt2 < 16; nt2++) {
                    int col = 8 * nt2 + g;
                    uint32_t b0 = fas(Vb[(krow + tig) * V_STR + col]);
                    uint32_t b1 = fas(Vb[(krow + 4 + tig) * V_STR + col]);
                    mma_tf32(of[nt2][0], of[nt2][1], of[nt2][2], of[nt2][3],
                             a0, a1, a2, a3, b0, b1);
                }
            }
        }
    }

    // ---- epilogue: reduce partial O across wc pairs + l; write RAW partials ----
    lsum0 += __shfl_xor_sync(0xffffffffu, lsum0, 1);
    lsum0 += __shfl_xor_sync(0xffffffffu, lsum0, 2);
    lsum1 += __shfl_xor_sync(0xffffffffu, lsum1, 1);
    lsum1 += __shfl_xor_sync(0xffffffffu, lsum1, 2);

    __syncthreads();
    float* part = sm + KS_OFF;
    float* Lp = sm + LP_OFF;
    {
        float* pw = part + wc * (64 * PART_STR);
        #pragma unroll
        for (int nt2 = 0; nt2 < 16; nt2++) {
            int col = 8 * nt2 + 2 * tig;
            *(float2*)&pw[(m0 + g) * PART_STR + col] =
                make_float2(of[nt2][0], of[nt2][1]);
            *(float2*)&pw[(m0 + g + 8) * PART_STR + col] =
                make_float2(of[nt2][2], of[nt2][3]);
        }
        if (tig == 0) {
            Lp[wc * 64 + m0 + g] = lsum0;
            Lp[wc * 64 + m0 + g + 8] = lsum1;
        }
    }
    __syncthreads();

    float* __restrict__ Oh = g_Op[half];
    float* __restrict__ lh = g_lp[half];
    if (t < 64)
        lh[(size_t)b * TSEQ + q0 + t] = Lp[t] + Lp[64 + t];

    float* __restrict__ o0 = Oh + ((size_t)b * TSEQ + qrow) * HS;
    float* __restrict__ o1 = Oh + ((size_t)b * TSEQ + qrow + 8) * HS;
    #pragma unroll
    for (int nt = 0; nt < 8; nt++) {
        int col = 64 * wc + 8 * nt + 2 * tig;
        float2 s0a = *(float2*)&part[(m0 + g) * PART_STR + col];
        float2 s0b = *(float2*)&part[64 * PART_STR + (m0 + g) * PART_STR + col];
        float2 s1a = *(float2*)&part[(m0 + g + 8) * PART_STR + col];
        float2 s1b = *(float2*)&part[64 * PART_STR + (m0 + g + 8) * PART_STR + col];
        *(float2*)&o0[col] = make_float2(s0a.x + s0b.x, s0a.y + s0b.y);
        *(float2*)&o1[col] = make_float2(s1a.x + s1b.x, s1a.y + s1b.y);
    }
}

// ============================================================================
// Combine: out = (O0 + O1) / (l0 + l1). 512K float4 elements.
// ============================================================================
__global__ __launch_bounds__(256)
void combine_kernel(float* __restrict__ out)
{
    const int idx = blockIdx.x * 256 + threadIdx.x;      // float4 index
    const int row = idx >> 5;                            // HS/4 = 32 per row
    float inv = 1.0f / (g_lp[0][row] + g_lp[1][row]);
    const float4* a = (const float4*)g_Op[0];
    const float4* b = (const float4*)g_Op[1];
    float4 va = a[idx], vb = b[idx];
    float4 v;
    v.x = (va.x + vb.x) * inv;
    v.y = (va.y + vb.y) * inv;
    v.z = (va.z + vb.z) * inv;
    v.w = (va.w + vb.w) * inv;
    ((float4*)out)[idx] = v;
}

extern "C" void kernel_launch(void* const* d_in, const int* in_sizes, int n_in,
                              void* d_out, int out_size)
{
    const float* x  = (const float*)d_in[0];
    const float* Wq = (const float*)d_in[1];
    const float* Wk = (const float*)d_in[2];
    const float* Wv = (const float*)d_in[3];
    float* out = (float*)d_out;

    cudaFuncSetAttribute(proj_kernel, cudaFuncAttributeMaxDynamicSharedMemorySize, SM_PROJ);
    cudaFuncSetAttribute(attn_kernel, cudaFuncAttributeMaxDynamicSharedMemorySize, SM_ATTN);

    proj_kernel<<<dim3(3, NROWS / 64), 128, SM_PROJ>>>(x, Wq, Wk, Wv);
    attn_kernel<<<(TSEQ / 64) * BATCH * 2, 256, SM_ATTN>>>();
    combine_kernel<<<(NROWS * HS / 4) / 256, 256>>>(out);
}